// round 16
// baseline (speedup 1.0000x reference)
#include <cuda_runtime.h>

// Cost volume s2: B=4, C=32, H=W=256, D=9, 8 groups of 4 channels.
// y-offset 0 -> 1D lerp in x; res span 0.8 < 1 px -> 3 taps/side cover all d.
// F folded into the lerp: a = wl-F = (P1-F) + t*S + |t|*Dd  (S=(P2-P0)/2,
// Dd=(P2+P0)/2-P1).  Pairwise variance:
//   cost = (1/18) * Sum_ci( a^2 + b^2 - a*b ),  b = wr-F.
// Block = one (b, row h, group PAIR), staged in SMEM as in R8 (bracketed
// optimal). NEW vs R8: both groups' operands built up front (8 channels,
// 48 regs) and ONE fused d-loop processes both groups per iteration --
// per-d t/|t| work shared, 8 independent FFMA2 chains for 2x ILP.
// launch_bounds(256,3): 85-reg ceiling gives ptxas room (R9 showed the
// 51-reg squeeze destroys ILP; this is the symmetric experiment).

typedef unsigned long long u64;

constexpr int Wd = 256, Cn = 32, Bn = 4, Dn = 9, Gn = 8, CPG = 4;
constexpr int HW = 256 * 256;
constexpr int RW = 268;          // padded SMEM row: 4 halo + 256 + 8 halo
constexpr int GPB = 2;           // groups per block
constexpr int CB  = GPB * CPG;   // 8 channels staged per block

__device__ __forceinline__ u64 pk(float a, float b) {
    u64 r; asm("mov.b64 %0, {%1, %2};" : "=l"(r) : "f"(a), "f"(b)); return r;
}
__device__ __forceinline__ void upk(float& a, float& b, u64 v) {
    asm("mov.b64 {%0, %1}, %2;" : "=f"(a), "=f"(b) : "l"(v));
}
__device__ __forceinline__ u64 ffma2(u64 a, u64 b, u64 c) {
    u64 d; asm("fma.rn.f32x2 %0, %1, %2, %3;" : "=l"(d) : "l"(a), "l"(b), "l"(c));
    return d;
}
__device__ __forceinline__ u64 add2(u64 a, u64 b) {
    u64 d; asm("add.rn.f32x2 %0, %1, %2;" : "=l"(d) : "l"(a), "l"(b));
    return d;
}

__global__ __launch_bounds__(256, 3) void cost_volume_kernel(
    const float* __restrict__ fref,
    const float* __restrict__ fls,
    const float* __restrict__ frs,
    const float* __restrict__ dinit,
    float* __restrict__ out)
{
    __shared__ float sL[CB][RW];
    __shared__ float sR[CB][RW];
    __shared__ float sF[CB][256];

    const int bid = blockIdx.x;          // B*H*(G/2) = 4096 blocks
    const int gp = bid & 3;              // group pair 0..3
    const int h  = (bid >> 2) & 255;
    const int b  = bid >> 10;
    const int tid = threadIdx.x;
    const int w = tid;

    // ---- Zero halos: 16 rows (8 L + 8 R) x 12 entries ----
    if (tid < 192) {
        const int r   = tid / 12;              // 0..15 : (ci8, arr)
        const int e   = tid % 12;
        const int off = (e < 4) ? e : (256 + e);
        float (*A)[RW] = (r & 1) ? sR : sL;
        A[r >> 1][off] = 0.0f;
    }

    // ---- Stage 24 rows (8ch x {L,R,F}) as 1536 float4, 6 per thread ----
    {
        const int rowg0 = b * Cn * HW + gp * CB * HW + h * 256;
        #pragma unroll
        for (int k = 0; k < 6; k++) {
            const int j     = tid + (k << 8);
            const int which = j >> 6;          // 0..23
            const int col4  = j & 63;
            const int ci8   = which & 7;
            const int arr   = which >> 3;      // 0=L 1=R 2=F
            const float* src = (arr == 0) ? fls : (arr == 1) ? frs : fref;
            const float4 v = __ldg((const float4*)(src + rowg0 + ci8 * HW) + col4);
            if (arr == 0)      *(float4*)&sL[ci8][4 + (col4 << 2)] = v;
            else if (arr == 1) *(float4*)&sR[ci8][4 + (col4 << 2)] = v;
            else               *(float4*)&sF[ci8][col4 << 2] = v;
        }
    }

    const float disp = __ldg(dinit + b * HW + h * 256 + w);
    const float wf = (float)w;

    // Left taps n_l..n_l+2, n_l = floor(x_l at d=0); x_l increases with d.
    const float xl0 = wf + disp - 0.4f;
    const float fll = floorf(xl0);
    const int   n_l = (int)fll;
    const float tl0 = xl0 - fll - 1.0f;
    // Right taps n_r..n_r+2, n_r = floor(x_r at d=8); x_r decreases with d.
    const float xr0 = wf - disp + 0.4f;
    const float flr = floorf(xr0 - 0.8f);
    const int   n_r = (int)flr;
    const float tr0 = xr0 - flr - 1.0f;

    const u64 t02   = pk(tl0, tr0);
    const u64 step2 = pk(0.1f, -0.1f);
    const u64 amask = 0x7FFFFFFF7FFFFFFFull;
    const int il = n_l + 4;
    const int ir = n_r + 4;
    const float c18 = 1.0f / 18.0f;

    __syncthreads();

    // ---- Gather taps for ALL 8 channels, build packed operands ----
    u64 P1F[CB], Sv[CB], Dd[CB];
    #pragma unroll
    for (int c8 = 0; c8 < CB; c8++) {
        const float L0 = sL[c8][il], L1 = sL[c8][il + 1], L2 = sL[c8][il + 2];
        const float R0 = sR[c8][ir], R1 = sR[c8][ir + 1], R2 = sR[c8][ir + 2];
        const float F  = sF[c8][w];

        P1F[c8] = pk(L1 - F, R1 - F);
        Sv[c8]  = pk(0.5f * (L2 - L0), 0.5f * (R2 - R0));
        Dd[c8]  = pk(fmaf(0.5f, L2 + L0, -L1), fmaf(0.5f, R2 + R0, -R1));
    }

    float* outp0 = out + b * (Gn * Dn * HW) + gp * GPB * Dn * HW + h * 256 + w;
    float* outp1 = outp0 + Dn * HW;

    // ---- Fused d-loop: both groups per iteration (8 independent chains) ----
    u64 t2 = t02;
    #pragma unroll
    for (int d = 0; d < 9; d++) {
        const u64 at2 = t2 & amask;            // (|t_l|, |t_r|) shared by groups

        u64 accP0 = 0ull, accP1 = 0ull;
        float ax0 = 0.0f, ax1 = 0.0f;
        #pragma unroll
        for (int ci = 0; ci < CPG; ci++) {
            const u64 lw0 = ffma2(t2, Sv[ci],
                            ffma2(at2, Dd[ci], P1F[ci]));
            const u64 lw1 = ffma2(t2, Sv[CPG + ci],
                            ffma2(at2, Dd[CPG + ci], P1F[CPG + ci]));
            accP0 = ffma2(lw0, lw0, accP0);
            accP1 = ffma2(lw1, lw1, accP1);
            float a0, b0; upk(a0, b0, lw0);
            float a1, b1; upk(a1, b1, lw1);
            ax0 = fmaf(a0, b0, ax0);
            ax1 = fmaf(a1, b1, ax1);
        }
        t2 = add2(t2, step2);

        float p0l, p0r; upk(p0l, p0r, accP0);
        float p1l, p1r; upk(p1l, p1r, accP1);
        __stcg(outp0 + d * HW, ((p0l + p0r) - ax0) * c18);
        __stcg(outp1 + d * HW, ((p1l + p1r) - ax1) * c18);
    }
}

extern "C" void kernel_launch(void* const* d_in, const int* in_sizes, int n_in,
                              void* d_out, int out_size)
{
    const float* fref  = (const float*)d_in[0];
    const float* fls   = (const float*)d_in[1];
    const float* frs   = (const float*)d_in[2];
    const float* dinit = (const float*)d_in[3];
    float* out = (float*)d_out;

    // blocks over (b, h, group-pair): 4 * 256 * 4 = 4096
    cost_volume_kernel<<<Bn * 256 * (Gn / GPB), 256>>>(fref, fls, frs, dinit, out);
}

// round 17
// speedup vs baseline: 1.0494x; 1.0494x over previous
#include <cuda_runtime.h>

// Cost volume s2: B=4, C=32, H=W=256, D=9, 8 groups of 4 channels.
// y-offset 0 -> 1D lerp in x; res span 0.8 < 1 px -> 3 taps/side cover all d.
// F folded into the lerp: a = wl-F = (P1-F) + t*S + |t|*Dd  (S=(P2-P0)/2,
// Dd=(P2+P0)/2-P1).  Pairwise variance:
//   cost = (1/18) * Sum_ci( a^2 + b^2 - a*b ),  b = wr-F.
// Block = one (b, ROW PAIR h..h+1, group PAIR): 512 threads, thread ->
// (hh = tid>>8, w = tid&255). Per-thread structure identical to the R8
// champion (GPB=2, 64 regs, 6 front-batched LDG.128 -- all bracketed-optimal);
// only the per-block fixed cost (halo, sync, scheduling) is amortized 2x.

typedef unsigned long long u64;

constexpr int Wd = 256, Cn = 32, Bn = 4, Dn = 9, Gn = 8, CPG = 4;
constexpr int HW = 256 * 256;
constexpr int RW = 268;          // padded SMEM row: 4 halo + 256 + 8 halo
constexpr int GPB = 2;           // groups per block
constexpr int CB  = GPB * CPG;   // 8 channels staged per block
constexpr int HB  = 2;           // h-rows per block
constexpr int NT  = 256 * HB;    // 512 threads

__device__ __forceinline__ u64 pk(float a, float b) {
    u64 r; asm("mov.b64 %0, {%1, %2};" : "=l"(r) : "f"(a), "f"(b)); return r;
}
__device__ __forceinline__ void upk(float& a, float& b, u64 v) {
    asm("mov.b64 {%0, %1}, %2;" : "=f"(a), "=f"(b) : "l"(v));
}
__device__ __forceinline__ u64 ffma2(u64 a, u64 b, u64 c) {
    u64 d; asm("fma.rn.f32x2 %0, %1, %2, %3;" : "=l"(d) : "l"(a), "l"(b), "l"(c));
    return d;
}
__device__ __forceinline__ u64 add2(u64 a, u64 b) {
    u64 d; asm("add.rn.f32x2 %0, %1, %2;" : "=l"(d) : "l"(a), "l"(b));
    return d;
}

__global__ __launch_bounds__(NT, 2) void cost_volume_kernel(
    const float* __restrict__ fref,
    const float* __restrict__ fls,
    const float* __restrict__ frs,
    const float* __restrict__ dinit,
    float* __restrict__ out)
{
    __shared__ float sL[HB][CB][RW];
    __shared__ float sR[HB][CB][RW];
    __shared__ float sF[HB][CB][256];

    const int bid = blockIdx.x;          // B*(H/2)*(G/2) = 2048 blocks
    const int gp = bid & 3;              // group pair 0..3
    const int hp = (bid >> 2) & 127;     // row pair
    const int b  = bid >> 9;
    const int tid = threadIdx.x;
    const int w  = tid & 255;
    const int hh = tid >> 8;             // 0..1
    const int h0 = hp * HB;

    // ---- Zero halos: 32 rows (2h x 8ch x {L,R}) x 12 entries = 384 ----
    if (tid < 384) {
        const int r   = tid / 12;              // 0..31
        const int e   = tid % 12;
        const int off = (e < 4) ? e : (256 + e);
        const int row16 = r >> 1;              // 0..15 : (hh2, ci8)
        if (r & 1) sR[row16 >> 3][row16 & 7][off] = 0.0f;
        else       sL[row16 >> 3][row16 & 7][off] = 0.0f;
    }

    // ---- Stage 48 rows (2h x 8ch x {L,R,F}) as 3072 float4, 6/thread ----
    {
        const int rowg0 = b * Cn * HW + gp * CB * HW + h0 * 256;
        #pragma unroll
        for (int k = 0; k < 6; k++) {
            const int j     = tid + k * NT;
            const int which = j >> 6;          // 0..47
            const int col4  = j & 63;
            const int arr   = which >> 4;      // 0=L 1=R 2=F
            const int ci8   = which & 7;
            const int hh2   = (which >> 3) & 1;
            const float* src = (arr == 0) ? fls : (arr == 1) ? frs : fref;
            const float4 v = __ldg(
                (const float4*)(src + rowg0 + ci8 * HW + hh2 * 256) + col4);
            if (arr == 0)      *(float4*)&sL[hh2][ci8][4 + (col4 << 2)] = v;
            else if (arr == 1) *(float4*)&sR[hh2][ci8][4 + (col4 << 2)] = v;
            else               *(float4*)&sF[hh2][ci8][col4 << 2] = v;
        }
    }

    const float disp = __ldg(dinit + b * HW + (h0 + hh) * 256 + w);
    const float wf = (float)w;

    // Left taps n_l..n_l+2, n_l = floor(x_l at d=0); x_l increases with d.
    const float xl0 = wf + disp - 0.4f;
    const float fll = floorf(xl0);
    const int   n_l = (int)fll;
    const float tl0 = xl0 - fll - 1.0f;
    // Right taps n_r..n_r+2, n_r = floor(x_r at d=8); x_r decreases with d.
    const float xr0 = wf - disp + 0.4f;
    const float flr = floorf(xr0 - 0.8f);
    const int   n_r = (int)flr;
    const float tr0 = xr0 - flr - 1.0f;

    const u64 t02   = pk(tl0, tr0);
    const u64 step2 = pk(0.1f, -0.1f);
    const u64 amask = 0x7FFFFFFF7FFFFFFFull;
    const int il = n_l + 4;
    const int ir = n_r + 4;
    const float c18 = 1.0f / 18.0f;

    __syncthreads();

    float* outbh = out + b * (Gn * Dn * HW) + gp * GPB * Dn * HW
                       + (h0 + hh) * 256 + w;

    #pragma unroll
    for (int gg = 0; gg < GPB; gg++) {
        // ---- Gather taps, build packed operands (F pre-subtracted) ----
        u64 P1F[CPG], Sv[CPG], Dd[CPG];
        #pragma unroll
        for (int ci = 0; ci < CPG; ci++) {
            const int c8 = gg * CPG + ci;
            const float L0 = sL[hh][c8][il], L1 = sL[hh][c8][il + 1],
                        L2 = sL[hh][c8][il + 2];
            const float R0 = sR[hh][c8][ir], R1 = sR[hh][c8][ir + 1],
                        R2 = sR[hh][c8][ir + 2];
            const float F  = sF[hh][c8][w];

            P1F[ci] = pk(L1 - F, R1 - F);
            Sv[ci]  = pk(0.5f * (L2 - L0), 0.5f * (R2 - R0));
            Dd[ci]  = pk(fmaf(0.5f, L2 + L0, -L1), fmaf(0.5f, R2 + R0, -R1));
        }

        float* outp = outbh + gg * Dn * HW;
        u64 t2 = t02;

        #pragma unroll
        for (int d = 0; d < 9; d++) {
            const u64 at2 = t2 & amask;        // (|t_l|, |t_r|)

            u64 accP = 0ull;
            float ax = 0.0f;
            #pragma unroll
            for (int ci = 0; ci < CPG; ci++) {
                const u64 lw = ffma2(t2, Sv[ci],
                               ffma2(at2, Dd[ci], P1F[ci]));
                accP = ffma2(lw, lw, accP);    // (S a^2, S b^2)
                float a, bb; upk(a, bb, lw);
                ax = fmaf(a, bb, ax);          // S a*b
            }
            t2 = add2(t2, step2);

            float aPl, aPr; upk(aPl, aPr, accP);
            __stcg(outp + d * HW, ((aPl + aPr) - ax) * c18);
        }
    }
}

extern "C" void kernel_launch(void* const* d_in, const int* in_sizes, int n_in,
                              void* d_out, int out_size)
{
    const float* fref  = (const float*)d_in[0];
    const float* fls   = (const float*)d_in[1];
    const float* frs   = (const float*)d_in[2];
    const float* dinit = (const float*)d_in[3];
    float* out = (float*)d_out;

    // blocks over (b, row-pair, group-pair): 4 * 128 * 4 = 2048
    cost_volume_kernel<<<Bn * (256 / HB) * (Gn / GPB), NT>>>(
        fref, fls, frs, dinit, out);
}